// round 14
// baseline (speedup 1.0000x reference)
#include <cuda_runtime.h>
#include <math.h>

// Problem constants (BS=16, Q=1024, K=256, T=128)
#define NROWS 16384   // BS*Q
#define KCLS  256     // num classes
#define MT    2048    // BS*T target columns
#define RPB   16      // rows (queries) per block in cost kernel
#define THREADS 256
#define MPT   8       // MT / THREADS targets per thread

// Scratch for softmax probabilities: 16384 x 256 f32 = 16.7 MB (static device array; no allocs)
__device__ float g_prob[(size_t)NROWS * KCLS];

// ---------------------------------------------------------------------------
// Pass 1: row softmax of pred_logits -> g_prob. One warp per row (K=256).
// ---------------------------------------------------------------------------
__global__ __launch_bounds__(256) void softmax_k(const float* __restrict__ logits) {
    int warp = (blockIdx.x * 256 + threadIdx.x) >> 5;   // row id
    int lane = threadIdx.x & 31;

    const float4* src = reinterpret_cast<const float4*>(logits) + (size_t)warp * 64;
    float4 a = src[lane];
    float4 b = src[lane + 32];

    float m = fmaxf(fmaxf(fmaxf(a.x, a.y), fmaxf(a.z, a.w)),
                    fmaxf(fmaxf(b.x, b.y), fmaxf(b.z, b.w)));
#pragma unroll
    for (int s = 16; s; s >>= 1) m = fmaxf(m, __shfl_xor_sync(0xffffffffu, m, s));

    a.x = __expf(a.x - m); a.y = __expf(a.y - m);
    a.z = __expf(a.z - m); a.w = __expf(a.w - m);
    b.x = __expf(b.x - m); b.y = __expf(b.y - m);
    b.z = __expf(b.z - m); b.w = __expf(b.w - m);

    float s = ((a.x + a.y) + (a.z + a.w)) + ((b.x + b.y) + (b.z + b.w));
#pragma unroll
    for (int sh = 16; sh; sh >>= 1) s += __shfl_xor_sync(0xffffffffu, s, sh);

    float inv;
    asm("rcp.approx.f32 %0, %1;" : "=f"(inv) : "f"(s));

    a.x *= inv; a.y *= inv; a.z *= inv; a.w *= inv;
    b.x *= inv; b.y *= inv; b.z *= inv; b.w *= inv;

    float4* dst = reinterpret_cast<float4*>(g_prob) + (size_t)warp * 64;
    dst[lane]      = a;
    dst[lane + 32] = b;
}

// ---------------------------------------------------------------------------
// Pass 2: cost matrix. Each block owns RPB=16 query rows; thread t owns target
// columns m = 8t .. 8t+7 (constants held in registers across all rows).
// Per row: stage the 1KB softmax row into double-buffered smem (one barrier
// per iteration), then each thread emits 8 costs as 2x STG.128 (coalesced).
//
// Math identities used (1 rcp per element, 3 min/max per element):
//   raw  = min(x1,t1) - max(x0,t0)
//   hull = (a1+a2) - raw          (exact: hull = max(x1,t1)-min(x0,t0))
//   inter= max(raw, 0)
//   union= (a1+a2) - inter
//   giou+1 = (inter*hull + union^2) / (union*hull)
//   C = 5*|dx0|+5*|dx1| - prob[label] + 2 - 2*(giou+1)
// ---------------------------------------------------------------------------
__global__ __launch_bounds__(THREADS) void cost_k(
    const float* __restrict__ pred_boxes,   // [NROWS,2] (mid, w)
    const float* __restrict__ tgt_boxes,    // [MT,2]    (x0, x1)
    const int*   __restrict__ tgt_labels,   // [MT]
    float*       __restrict__ out)          // [NROWS, MT]
{
    __shared__ float sprob[2][KCLS];

    const int t  = threadIdx.x;
    const int m0 = t * MPT;

    // Per-thread target constants (registers)
    float t0[MPT], t1[MPT], a2[MPT];
    int   lab[MPT];
    const float2* tb = reinterpret_cast<const float2*>(tgt_boxes);
#pragma unroll
    for (int j = 0; j < MPT; j++) {
        float2 bb = tb[m0 + j];
        t0[j] = bb.x;
        t1[j] = bb.y;
        a2[j] = bb.y - bb.x;
        lab[j] = tgt_labels[m0 + j];
    }

    const int nbase = blockIdx.x * RPB;
    const float2* pbv = reinterpret_cast<const float2*>(pred_boxes);

    for (int r = 0; r < RPB; r++) {
        const int n   = nbase + r;
        const int buf = r & 1;

        // Stage softmax row (1KB) into smem
        if (t < 64) {
            reinterpret_cast<float4*>(sprob[buf])[t] =
                reinterpret_cast<const float4*>(g_prob + (size_t)n * KCLS)[t];
        }
        float2 pb = pbv[n];                       // uniform broadcast load
        const float x0 = fmaf(-0.5f, pb.y, pb.x);
        const float x1 = fmaf( 0.5f, pb.y, pb.x);
        const float a1 = pb.y;

        __syncthreads();  // buf[r&1] ready; also guarantees compute of row r-1 done
                          // before row r+1's load overwrites buf[(r+1)&1]=buf[(r-1)&1]

        float res[MPT];
#pragma unroll
        for (int j = 0; j < MPT; j++) {
            const float cls = sprob[buf][lab[j]];
            const float d   = fabsf(x0 - t0[j]) + fabsf(x1 - t1[j]);

            const float mn1  = fminf(x1, t1[j]);
            const float mx0  = fmaxf(x0, t0[j]);
            const float raw  = mn1 - mx0;
            const float a12  = a1 + a2[j];
            const float hull = a12 - raw;             // > 0 always (widths > 0)
            const float inter = fmaxf(raw, 0.0f);
            const float uni   = a12 - inter;          // > 0 always

            float rcp;
            asm("rcp.approx.f32 %0, %1;" : "=f"(rcp) : "f"(uni * hull));
            const float g1 = fmaf(uni, uni, inter * hull) * rcp;  // giou + 1

            // C = 5*d - cls + 2 - 2*g1
            res[j] = fmaf(-2.0f, g1, fmaf(5.0f, d, 2.0f - cls));
        }

        float4* o = reinterpret_cast<float4*>(out + (size_t)n * MT + m0);
        o[0] = make_float4(res[0], res[1], res[2], res[3]);
        o[1] = make_float4(res[4], res[5], res[6], res[7]);
    }
}

// ---------------------------------------------------------------------------
// Launch: graph-capturable, allocation-free, deterministic.
// Inputs (metadata order): pred_logits, pred_boxes, tgt_boxes, tgt_labels.
// ---------------------------------------------------------------------------
extern "C" void kernel_launch(void* const* d_in, const int* in_sizes, int n_in,
                              void* d_out, int out_size) {
    const float* logits  = (const float*)d_in[0];
    const float* pboxes  = (const float*)d_in[1];
    const float* tboxes  = (const float*)d_in[2];
    const int*   tlabels = (const int*)d_in[3];
    float* out = (float*)d_out;

    softmax_k<<<NROWS / 8, 256>>>(logits);                 // 2048 blocks, warp/row
    cost_k<<<NROWS / RPB, THREADS>>>(pboxes, tboxes, tlabels, out);  // 1024 blocks
}

// round 15
// speedup vs baseline: 1.3155x; 1.3155x over previous
#include <cuda_runtime.h>
#include <math.h>

// Problem constants (BS=16, Q=1024, K=256, T=128)
#define NROWS 16384   // BS*Q
#define KCLS  256     // num classes
#define MT    2048    // BS*T target columns
#define RPB   16      // rows (queries) per block
#define THREADS 256   // 8 warps
#define MPT   8       // MT / THREADS targets per thread

// ---------------------------------------------------------------------------
// Fused kernel: per block of 16 query rows
//   Phase 1 (prologue): 8 warps compute 16 row-softmaxes (2 rows/warp) of
//     pred_logits directly into smem sprob[16][256]; pred boxes staged to smem.
//   Phase 2 (after ONE __syncthreads): thread t owns target columns
//     m = 8t..8t+7 (constants in registers), loops 16 rows sync-free,
//     emits 2x STG.128 per row (fully coalesced).
//
// Math identities (1 rcp.approx + 3 FMNMX per element):
//   raw   = min(x1,t1) - max(x0,t0)
//   hull  = (a1+a2) - raw            (== max(x1,t1)-min(x0,t0), > 0)
//   inter = max(raw, 0)
//   union = (a1+a2) - inter          (> 0)
//   giou+1 = (inter*hull + union^2) / (union*hull)
//   C = 5*(|dx0|+|dx1|) - prob[label] + 2 - 2*(giou+1)
// ---------------------------------------------------------------------------
__global__ __launch_bounds__(THREADS) void fused_cost_k(
    const float* __restrict__ pred_logits,  // [NROWS, KCLS]
    const float* __restrict__ pred_boxes,   // [NROWS, 2] (mid, w)
    const float* __restrict__ tgt_boxes,    // [MT, 2]    (x0, x1)
    const int*   __restrict__ tgt_labels,   // [MT]
    float*       __restrict__ out)          // [NROWS, MT]
{
    __shared__ float sprob[RPB][KCLS];      // 16 KB
    __shared__ float2 s_pb[RPB];            // (mid, w) per row

    const int t    = threadIdx.x;
    const int lane = t & 31;
    const int w    = t >> 5;
    const int m0   = t * MPT;
    const int nbase = blockIdx.x * RPB;

    // ---- Per-thread target constants (live across the whole kernel) ----
    float t0[MPT], t1[MPT], a2[MPT];
    int   lab[MPT];
    {
        const float2* tb = reinterpret_cast<const float2*>(tgt_boxes);
#pragma unroll
        for (int j = 0; j < MPT; j++) {
            float2 bb = tb[m0 + j];
            t0[j] = bb.x;
            t1[j] = bb.y;
            a2[j] = bb.y - bb.x;
            lab[j] = tgt_labels[m0 + j];
        }
    }

    // ---- Phase 1: softmax of 16 rows into smem (2 rows per warp) ----
    if (t < RPB) {
        s_pb[t] = reinterpret_cast<const float2*>(pred_boxes)[nbase + t];
    }
#pragma unroll
    for (int rr = 0; rr < 2; rr++) {
        const int row = w * 2 + rr;
        const float4* src = reinterpret_cast<const float4*>(
            pred_logits + (size_t)(nbase + row) * KCLS);
        float4 a = src[lane];
        float4 b = src[lane + 32];

        float m = fmaxf(fmaxf(fmaxf(a.x, a.y), fmaxf(a.z, a.w)),
                        fmaxf(fmaxf(b.x, b.y), fmaxf(b.z, b.w)));
#pragma unroll
        for (int s = 16; s; s >>= 1) m = fmaxf(m, __shfl_xor_sync(0xffffffffu, m, s));

        a.x = __expf(a.x - m); a.y = __expf(a.y - m);
        a.z = __expf(a.z - m); a.w = __expf(a.w - m);
        b.x = __expf(b.x - m); b.y = __expf(b.y - m);
        b.z = __expf(b.z - m); b.w = __expf(b.w - m);

        float s = ((a.x + a.y) + (a.z + a.w)) + ((b.x + b.y) + (b.z + b.w));
#pragma unroll
        for (int sh = 16; sh; sh >>= 1) s += __shfl_xor_sync(0xffffffffu, s, sh);

        float inv;
        asm("rcp.approx.f32 %0, %1;" : "=f"(inv) : "f"(s));

        a.x *= inv; a.y *= inv; a.z *= inv; a.w *= inv;
        b.x *= inv; b.y *= inv; b.z *= inv; b.w *= inv;

        float4* dst = reinterpret_cast<float4*>(sprob[row]);
        dst[lane]      = a;
        dst[lane + 32] = b;
    }

    __syncthreads();   // the ONLY barrier

    // ---- Phase 2: 16 rows of cost computation, sync-free ----
#pragma unroll 2
    for (int r = 0; r < RPB; r++) {
        const float2 pb = s_pb[r];                 // broadcast LDS
        const float x0 = fmaf(-0.5f, pb.y, pb.x);
        const float x1 = fmaf( 0.5f, pb.y, pb.x);
        const float a1 = pb.y;
        const float* pr = sprob[r];

        float res[MPT];
#pragma unroll
        for (int j = 0; j < MPT; j++) {
            const float cls = pr[lab[j]];
            const float d   = fabsf(x0 - t0[j]) + fabsf(x1 - t1[j]);

            const float mn1  = fminf(x1, t1[j]);
            const float mx0  = fmaxf(x0, t0[j]);
            const float raw  = mn1 - mx0;
            const float a12  = a1 + a2[j];
            const float hull = a12 - raw;
            const float inter = fmaxf(raw, 0.0f);
            const float uni   = a12 - inter;

            float rcp;
            asm("rcp.approx.f32 %0, %1;" : "=f"(rcp) : "f"(uni * hull));
            const float g1 = fmaf(uni, uni, inter * hull) * rcp;  // giou + 1

            // C = 5*d - cls + 2 - 2*g1
            res[j] = fmaf(-2.0f, g1, fmaf(5.0f, d, 2.0f - cls));
        }

        float4* o = reinterpret_cast<float4*>(out + (size_t)(nbase + r) * MT + m0);
        o[0] = make_float4(res[0], res[1], res[2], res[3]);
        o[1] = make_float4(res[4], res[5], res[6], res[7]);
    }
}

// ---------------------------------------------------------------------------
// Launch: graph-capturable, allocation-free, deterministic.
// Inputs (metadata order): pred_logits, pred_boxes, tgt_boxes, tgt_labels.
// ---------------------------------------------------------------------------
extern "C" void kernel_launch(void* const* d_in, const int* in_sizes, int n_in,
                              void* d_out, int out_size) {
    const float* logits  = (const float*)d_in[0];
    const float* pboxes  = (const float*)d_in[1];
    const float* tboxes  = (const float*)d_in[2];
    const int*   tlabels = (const int*)d_in[3];
    float* out = (float*)d_out;

    fused_cost_k<<<NROWS / RPB, THREADS>>>(logits, pboxes, tboxes, tlabels, out);
}

// round 17
// speedup vs baseline: 1.3908x; 1.0572x over previous
#include <cuda_runtime.h>
#include <math.h>

// Problem constants (BS=16, Q=1024, K=256, T=128)
#define NROWS 16384   // BS*Q
#define KCLS  256     // num classes
#define MT    2048    // BS*T target columns
#define RPB   16      // rows (queries) per block
#define THREADS 256   // 8 warps
#define MPT   8       // MT / THREADS targets per thread

// ---------------------------------------------------------------------------
// Fused kernel, one barrier.
//
// Key algebra (1-D intervals, widths > 0), exact in both overlap/disjoint:
//   s = a1 + a2,  d = |x0-t0| + |x1-t1|
//   min(x1,t1) - max(x0,t0) = (s-d)/2
//   giou = (s-d)/(s+d)
//   C = 5d - cls - 2*giou = 5d - (cls + 2) + 4d/(s+d)
// The "+2" is folded into the smem table: sprob holds softmax+2.
// ---------------------------------------------------------------------------
__global__ __launch_bounds__(THREADS) void fused_cost_k(
    const float* __restrict__ pred_logits,  // [NROWS, KCLS]
    const float* __restrict__ pred_boxes,   // [NROWS, 2] (mid, w)
    const float* __restrict__ tgt_boxes,    // [MT, 2]    (x0, x1)
    const int*   __restrict__ tgt_labels,   // [MT]
    float*       __restrict__ out)          // [NROWS, MT]
{
    __shared__ float sprob[RPB][KCLS];      // 16 KB, holds softmax + 2
    __shared__ float2 s_pb[RPB];            // (mid, w) per row

    const int t    = threadIdx.x;
    const int lane = t & 31;
    const int w    = t >> 5;
    const int m0   = t * MPT;
    const int nbase = blockIdx.x * RPB;

    // ---- Per-thread target constants (registers, live whole kernel) ----
    float nt0[MPT], nt1[MPT], a2[MPT];
    int   lab[MPT];
    {
        const float2* tb = reinterpret_cast<const float2*>(tgt_boxes);
#pragma unroll
        for (int j = 0; j < MPT; j++) {
            float2 bb = tb[m0 + j];
            nt0[j] = -bb.x;
            nt1[j] = -bb.y;
            a2[j]  = bb.y - bb.x;
            lab[j] = tgt_labels[m0 + j];
        }
    }

    // ---- Phase 1: softmax(+2) of 16 rows into smem (2 rows per warp) ----
    if (t < RPB) {
        s_pb[t] = reinterpret_cast<const float2*>(pred_boxes)[nbase + t];
    }
#pragma unroll
    for (int rr = 0; rr < 2; rr++) {
        const int row = w * 2 + rr;
        const float4* src = reinterpret_cast<const float4*>(
            pred_logits + (size_t)(nbase + row) * KCLS);
        float4 a = src[lane];
        float4 b = src[lane + 32];

        float m = fmaxf(fmaxf(fmaxf(a.x, a.y), fmaxf(a.z, a.w)),
                        fmaxf(fmaxf(b.x, b.y), fmaxf(b.z, b.w)));
#pragma unroll
        for (int s = 16; s; s >>= 1) m = fmaxf(m, __shfl_xor_sync(0xffffffffu, m, s));

        a.x = __expf(a.x - m); a.y = __expf(a.y - m);
        a.z = __expf(a.z - m); a.w = __expf(a.w - m);
        b.x = __expf(b.x - m); b.y = __expf(b.y - m);
        b.z = __expf(b.z - m); b.w = __expf(b.w - m);

        float s = ((a.x + a.y) + (a.z + a.w)) + ((b.x + b.y) + (b.z + b.w));
#pragma unroll
        for (int sh = 16; sh; sh >>= 1) s += __shfl_xor_sync(0xffffffffu, s, sh);

        float inv;
        asm("rcp.approx.f32 %0, %1;" : "=f"(inv) : "f"(s));

        // store softmax + 2 (folds the GIoU constant into the table; FFMA not FMUL)
        a.x = fmaf(a.x, inv, 2.0f); a.y = fmaf(a.y, inv, 2.0f);
        a.z = fmaf(a.z, inv, 2.0f); a.w = fmaf(a.w, inv, 2.0f);
        b.x = fmaf(b.x, inv, 2.0f); b.y = fmaf(b.y, inv, 2.0f);
        b.z = fmaf(b.z, inv, 2.0f); b.w = fmaf(b.w, inv, 2.0f);

        float4* dst = reinterpret_cast<float4*>(sprob[row]);
        dst[lane]      = a;
        dst[lane + 32] = b;
    }

    __syncthreads();   // the ONLY barrier

    // ---- Phase 2: 16 rows, sync-free ----
#pragma unroll 2
    for (int r = 0; r < RPB; r++) {
        const float2 pb = s_pb[r];
        const float x0 = fmaf(-0.5f, pb.y, pb.x);
        const float x1 = fmaf( 0.5f, pb.y, pb.x);
        const float a1 = pb.y;
        const float* pr = sprob[r];

        // Batch the 8 gathers first (MLP on the LDS pipe)
        float cls2[MPT];
#pragma unroll
        for (int j = 0; j < MPT; j++) cls2[j] = pr[lab[j]];   // = prob + 2

        float res[MPT];
#pragma unroll
        for (int j = 0; j < MPT; j++) {
            const float u0 = x0 + nt0[j];                  // FADD
            const float u1 = x1 + nt1[j];                  // FADD
            const float d  = fabsf(u0) + fabsf(u1);        // FADD
            const float den = (a1 + a2[j]) + d;            // 2x FADD

            float rcp;
            asm("rcp.approx.f32 %0, %1;" : "=f"(rcp) : "f"(den));   // MUFU

            const float base = fmaf(5.0f, d, -cls2[j]);    // FFMA: 5d - cls - 2
            res[j] = fmaf(4.0f, d * rcp, base);            // FMUL + FFMA
        }

        float4* o = reinterpret_cast<float4*>(out + (size_t)(nbase + r) * MT + m0);
        o[0] = make_float4(res[0], res[1], res[2], res[3]);
        o[1] = make_float4(res[4], res[5], res[6], res[7]);
    }
}

// ---------------------------------------------------------------------------
// Launch: graph-capturable, allocation-free, deterministic.
// Inputs (metadata order): pred_logits, pred_boxes, tgt_boxes, tgt_labels.
// ---------------------------------------------------------------------------
extern "C" void kernel_launch(void* const* d_in, const int* in_sizes, int n_in,
                              void* d_out, int out_size) {
    const float* logits  = (const float*)d_in[0];
    const float* pboxes  = (const float*)d_in[1];
    const float* tboxes  = (const float*)d_in[2];
    const int*   tlabels = (const int*)d_in[3];
    float* out = (float*)d_out;

    fused_cost_k<<<NROWS / RPB, THREADS>>>(logits, pboxes, tboxes, tlabels, out);
}